// round 15
// baseline (speedup 1.0000x reference)
#include <cuda_runtime.h>
#include <cuda_bf16.h>

#define FULL 0xFFFFFFFFu

constexpr int BATCH = 4096;
constexpr int DIM   = 32;
constexpr int N_MEM = 32;
constexpr int N_REL = 64;
constexpr int NCOL  = N_REL * DIM;   // 2048

// Static scratch (no runtime allocation allowed).
__device__ float          g_item[BATCH * DIM];
__device__ unsigned       g_Afrag[(BATCH / 16) * 2 * 32 * 4];   // A MMA frags
__device__ unsigned       g_Bfrag[(NCOL / 64) * 8 * 32 * 4];    // B MMA frags
__device__ float          g_Wt[DIM * DIM];
__device__ float          g_y[BATCH * DIM];

__device__ __forceinline__ float bf_lo(unsigned u) { return __uint_as_float(u << 16); }
__device__ __forceinline__ float bf_hi(unsigned u) { return __uint_as_float(u & 0xFFFF0000u); }

// Scatter one bf16 of the item vector into A-fragment layout (R8-proven).
__device__ __forceinline__ void afrag_store(int b, int e, float v) {
    const int mg = b >> 4, r = b & 15;
    const int h  = e >> 4, k = e & 15, kp = k >> 1;
    const int sel = ((r >> 3) & 1) + 2 * (kp >> 2);
    const int l   = (r & 7) * 4 + (kp & 3);
    const int idx = ((mg * 2 + h) * 32 + l) * 4 + sel;
    ((__nv_bfloat16*)g_Afrag)[idx * 2 + (k & 1)] = __float2bfloat16(v);
}

// ---------------------------------------------------------------- prep
__global__ void prep_kernel(const int* __restrict__ items,
                            const float* __restrict__ entity,
                            const float* __restrict__ relation,
                            const float* __restrict__ W) {
    const int i = blockIdx.x * blockDim.x + threadIdx.x;
    if (i < BATCH * DIM) {
        const int b = i >> 5, e = i & 31;
        const float v = entity[items[b] * DIM + e];
        g_item[i] = v;
        afrag_store(b, e, v);
    }
    if (i < (NCOL / 64) * 8 * 32 * 4) {
        const int nt = i >> 10, j = (i >> 7) & 7, l = (i >> 2) & 31, s = i & 3;
        const int n = nt * 64 + 8 * j + (l >> 2);
        const int r = n >> 5, e = n & 31;
        const int k0 = 2 * (l & 3) + 8 * s;
        const __nv_bfloat16 lo = __float2bfloat16(relation[r * 1024 + k0 * DIM + e]);
        const __nv_bfloat16 hi = __float2bfloat16(relation[r * 1024 + (k0 + 1) * DIM + e]);
        g_Bfrag[i] = ((unsigned)__bfloat16_as_ushort(hi) << 16) |
                     (unsigned)__bfloat16_as_ushort(lo);
    }
    if (i < DIM * DIM) {
        const int d = i >> 5, e = i & 31;
        g_Wt[e * DIM + d] = W[i];
    }
}

// ---------------------------------------------------------------- fused hop
__device__ __forceinline__ void mma16816(float c[4], const unsigned* a,
                                         unsigned b0, unsigned b1) {
    asm volatile(
        "mma.sync.aligned.m16n8k16.row.col.f32.bf16.bf16.f32 "
        "{%0,%1,%2,%3}, {%4,%5,%6,%7}, {%8,%9}, {%0,%1,%2,%3};\n"
        : "+f"(c[0]), "+f"(c[1]), "+f"(c[2]), "+f"(c[3])
        : "r"(a[0]), "r"(a[1]), "r"(a[2]), "r"(a[3]), "r"(b0), "r"(b1));
}

constexpr int USTR     = 4112;            // bytes per smem U row (4096 + 16 pad)
constexpr int U_BYTES  = 16 * USTR;       // 65792
constexpr int P_OFF    = U_BYTES;
constexpr int SMEM_TOT = U_BYTES + 8 * 2 * (N_MEM * 9) * 4;   // 84224 B

// Block = 16 batch elems, 256 threads. Phase 1: warp w computes U cols
// [w*256, (w+1)*256) for all 16 rows into smem. Phase 2: warp w does ILP-2
// attention for b = base+2w, base+2w+1 reading U from smem.
__global__ void __launch_bounds__(256) hop_kernel(
    const int* __restrict__ mem_h,
    const int* __restrict__ mem_r,
    const int* __restrict__ mem_t,
    const int* __restrict__ users,
    const float* __restrict__ entity,
    const float* __restrict__ user_table,
    float* __restrict__ out,
    int hop, int last)
{
    extern __shared__ __align__(16) char smem[];

    const int lane = threadIdx.x & 31;
    const int warp = threadIdx.x >> 5;
    const int bbase = blockIdx.x * 16;

    // ================= phase 1: U(16 x 2048) into smem =================
    {
        const uint4* __restrict__ Af = (const uint4*)g_Afrag;
        const uint4* __restrict__ Bf = (const uint4*)g_Bfrag;
        const int mg = blockIdx.x;
        const uint4 qa0 = Af[(mg * 2 + 0) * 32 + lane];   // k 0-15
        const uint4 qa1 = Af[(mg * 2 + 1) * 32 + lane];   // k 16-31

        const int fr = lane >> 2;              // fragment row 0..7
        const int cp = 4 * (lane & 3);         // byte offset of colpair in 8-col grp

        #pragma unroll
        for (int t = 0; t < 4; ++t) {
            const int nt = warp * 4 + t;
            #pragma unroll
            for (int j = 0; j < 8; ++j) {
                const uint4 qb = Bf[(nt * 8 + j) * 32 + lane];
                float c[4] = {0.f, 0.f, 0.f, 0.f};
                mma16816(c, (const unsigned*)&qa0, qb.x, qb.y);
                mma16816(c, (const unsigned*)&qa1, qb.z, qb.w);
                const __nv_bfloat162 p01 = __float22bfloat162_rn(make_float2(c[0], c[1]));
                const __nv_bfloat162 p23 = __float22bfloat162_rn(make_float2(c[2], c[3]));
                const int colb = (nt * 64 + 8 * j) * 2 + cp;
                *(__nv_bfloat162*)(smem + fr * USTR + colb)       = p01;
                *(__nv_bfloat162*)(smem + (fr + 8) * USTR + colb) = p23;
            }
        }
    }
    __syncthreads();

    // ================= phase 2: attention, 2 b per warp (ILP-2) =================
    const int b0 = bbase + warp * 2;
    const int b1 = b0 + 1;
    const char* __restrict__ U0 = smem + (warp * 2) * USTR;
    const char* __restrict__ U1 = U0 + USTR;
    float* __restrict__ P0 = (float*)(smem + P_OFF) + warp * (2 * N_MEM * 9);
    float* __restrict__ P1 = P0 + N_MEM * 9;

    const int base0 = hop * BATCH * N_MEM + b0 * N_MEM;
    const int base1 = base0 + N_MEM;
    const int hidx0 = mem_h[base0 + lane], hidx1 = mem_h[base1 + lane];
    const int ridx0 = mem_r[base0 + lane], ridx1 = mem_r[base1 + lane];
    const int tidx0 = mem_t[base0 + lane], tidx1 = mem_t[base1 + lane];

    const float item0 = g_item[b0 * DIM + lane];
    const float item1 = g_item[b1 * DIM + lane];

    const int mq = lane >> 3;
    const int c  = lane & 7;

    #pragma unroll
    for (int ss = 0; ss < 4; ++ss) {
        uint2  uu0[2], uu1[2];
        float4 h40[2], h41[2];
        #pragma unroll
        for (int it = 0; it < 2; ++it) {
            const int m = ss * 8 + it * 4 + mq;
            const int r0 = __shfl_sync(FULL, ridx0, m);
            const int h0 = __shfl_sync(FULL, hidx0, m);
            const int r1 = __shfl_sync(FULL, ridx1, m);
            const int h1 = __shfl_sync(FULL, hidx1, m);
            uu0[it] = *(const uint2*)(U0 + (r0 * DIM + 4 * c) * 2);
            h40[it] = *(const float4*)(entity + h0 * DIM + 4 * c);
            uu1[it] = *(const uint2*)(U1 + (r1 * DIM + 4 * c) * 2);
            h41[it] = *(const float4*)(entity + h1 * DIM + 4 * c);
        }
        #pragma unroll
        for (int it = 0; it < 2; ++it) {
            const int m = ss * 8 + it * 4 + mq;
            P0[m * 9 + c] = bf_lo(uu0[it].x) * h40[it].x + bf_hi(uu0[it].x) * h40[it].y +
                            bf_lo(uu0[it].y) * h40[it].z + bf_hi(uu0[it].y) * h40[it].w;
            P1[m * 9 + c] = bf_lo(uu1[it].x) * h41[it].x + bf_hi(uu1[it].x) * h41[it].y +
                            bf_lo(uu1[it].y) * h41[it].z + bf_hi(uu1[it].y) * h41[it].w;
        }
    }
    __syncwarp();

    float lg0 = 0.f, lg1 = 0.f;
    #pragma unroll
    for (int j = 0; j < 8; ++j) { lg0 += P0[lane * 9 + j]; lg1 += P1[lane * 9 + j]; }

    float mx0 = lg0, mx1 = lg1;
    #pragma unroll
    for (int off = 16; off; off >>= 1) {
        mx0 = fmaxf(mx0, __shfl_xor_sync(FULL, mx0, off));
        mx1 = fmaxf(mx1, __shfl_xor_sync(FULL, mx1, off));
    }
    const float ex0 = __expf(lg0 - mx0);
    const float ex1 = __expf(lg1 - mx1);
    float dn0 = ex0, dn1 = ex1;
    #pragma unroll
    for (int off = 16; off; off >>= 1) {
        dn0 += __shfl_xor_sync(FULL, dn0, off);
        dn1 += __shfl_xor_sync(FULL, dn1, off);
    }
    const float prob0 = ex0 / dn0;
    const float prob1 = ex1 / dn1;

    float o0 = 0.f, o1 = 0.f;
    #pragma unroll 8
    for (int m = 0; m < N_MEM; ++m) {
        const int t0 = __shfl_sync(FULL, tidx0, m);
        const int t1 = __shfl_sync(FULL, tidx1, m);
        const float p0 = __shfl_sync(FULL, prob0, m);
        const float p1 = __shfl_sync(FULL, prob1, m);
        o0 = fmaf(p0, entity[t0 * DIM + lane], o0);
        o1 = fmaf(p1, entity[t1 * DIM + lane], o1);
    }

    const float tmp0 = item0 + o0, tmp1 = item1 + o1;
    float itn0 = 0.f, itn1 = 0.f;
    #pragma unroll
    for (int e = 0; e < DIM; ++e) {
        const float w = g_Wt[e * DIM + lane];
        itn0 = fmaf(__shfl_sync(FULL, tmp0, e), w, itn0);
        itn1 = fmaf(__shfl_sync(FULL, tmp1, e), w, itn1);
    }

    if (!last) {
        g_item[b0 * DIM + lane] = itn0;
        g_item[b1 * DIM + lane] = itn1;
        g_y[b0 * DIM + lane] = o0;
        g_y[b1 * DIM + lane] = o1;
        afrag_store(b0, lane, itn0);        // next hop's A fragments
        afrag_store(b1, lane, itn1);
    } else {
        const float y0 = g_y[b0 * DIM + lane] + o0 + user_table[users[b0] * DIM + lane];
        const float y1 = g_y[b1 * DIM + lane] + o1 + user_table[users[b1] * DIM + lane];
        float s0 = itn0 * y0, s1 = itn1 * y1;
        #pragma unroll
        for (int off = 16; off; off >>= 1) {
            s0 += __shfl_xor_sync(FULL, s0, off);
            s1 += __shfl_xor_sync(FULL, s1, off);
        }
        if (lane == 0) {
            out[b0] = 1.f / (1.f + __expf(-s0));
            out[b1] = 1.f / (1.f + __expf(-s1));
        }
    }
}

// ---------------------------------------------------------------- launch
extern "C" void kernel_launch(void* const* d_in, const int* in_sizes, int n_in,
                              void* d_out, int out_size) {
    const int*   items     = (const int*)d_in[0];
    const int*   mem_h     = (const int*)d_in[2];
    const int*   mem_r     = (const int*)d_in[3];
    const int*   mem_t     = (const int*)d_in[4];
    const int*   users     = (const int*)d_in[5];
    const float* entity    = (const float*)d_in[6];
    const float* relation  = (const float*)d_in[7];
    const float* user_tab  = (const float*)d_in[8];
    const float* W         = (const float*)d_in[9];
    float* out = (float*)d_out;

    cudaFuncSetAttribute(hop_kernel,
                         cudaFuncAttributeMaxDynamicSharedMemorySize, SMEM_TOT);

    prep_kernel<<<(BATCH * DIM + 255) / 256, 256>>>(items, entity, relation, W);

    hop_kernel<<<BATCH / 16, 256, SMEM_TOT>>>(mem_h, mem_r, mem_t, users,
                                              entity, user_tab, out, 0, 0);
    hop_kernel<<<BATCH / 16, 256, SMEM_TOT>>>(mem_h, mem_r, mem_t, users,
                                              entity, user_tab, out, 1, 1);
}

// round 16
// speedup vs baseline: 1.1467x; 1.1467x over previous
#include <cuda_runtime.h>
#include <cuda_bf16.h>

#define FULL 0xFFFFFFFFu

constexpr int BATCH = 4096;
constexpr int DIM   = 32;
constexpr int N_MEM = 32;
constexpr int N_REL = 64;
constexpr int NCOL  = N_REL * DIM;   // 2048

// Static scratch (no runtime allocation allowed).
__device__ __nv_bfloat16  g_U[BATCH * NCOL];        // 16 MB bf16, LINEAR [b][n]
__device__ float          g_item[BATCH * DIM];
__device__ unsigned       g_Afrag[(BATCH / 16) * 2 * 32 * 4];   // A MMA frags
__device__ unsigned       g_Bfrag[(NCOL / 64) * 8 * 32 * 4];    // B MMA frags
__device__ float          g_Wt[DIM * DIM];
__device__ float          g_y[BATCH * DIM];

__device__ __forceinline__ float bf_lo(unsigned u) { return __uint_as_float(u << 16); }
__device__ __forceinline__ float bf_hi(unsigned u) { return __uint_as_float(u & 0xFFFF0000u); }

// Scatter one bf16 of the item vector into A-fragment layout (R8-proven).
__device__ __forceinline__ void afrag_store(int b, int e, float v) {
    const int mg = b >> 4, r = b & 15;
    const int h  = e >> 4, k = e & 15, kp = k >> 1;
    const int sel = ((r >> 3) & 1) + 2 * (kp >> 2);
    const int l   = (r & 7) * 4 + (kp & 3);
    const int idx = ((mg * 2 + h) * 32 + l) * 4 + sel;
    ((__nv_bfloat16*)g_Afrag)[idx * 2 + (k & 1)] = __float2bfloat16(v);
}

// Inverse B-fragment map: element relation[r*1024 + k*32 + e] -> Bfrag slot.
// Forward map (R8): u32 index i: nt=i>>10, j=(i>>7)&7, l=(i>>2)&31, s=i&3;
//   n = nt*64 + 8j + (l>>2); k0 = 2(l&3) + 8s; lo half=k0, hi half=k0+1.
__device__ __forceinline__ void bfrag_scatter(int r, int k, int e, float v) {
    const int n    = r * DIM + e;
    const int nt   = n >> 6;
    const int nrow = n & 63;
    const int j    = nrow >> 3;
    const int l    = (nrow & 7) * 4 + ((k & 7) >> 1);
    const int s    = k >> 3;
    const int u32i = ((nt * 8 + j) * 32 + l) * 4 + s;
    ((__nv_bfloat16*)g_Bfrag)[u32i * 2 + (k & 1)] = __float2bfloat16(v);
}

// ---------------------------------------------------------------- prep
__global__ void prep_kernel(const int* __restrict__ items,
                            const float* __restrict__ entity,
                            const float* __restrict__ relation,
                            const float* __restrict__ W) {
    const int i = blockIdx.x * blockDim.x + threadIdx.x;
    if (i < BATCH * DIM) {
        const int b = i >> 5, e = i & 31;
        const float v = entity[items[b] * DIM + e];
        g_item[i] = v;
        afrag_store(b, e, v);
    }
    // Bfrag: COALESCED float4 loads over relation's linear layout,
    // scattered 2-byte stores into fragment slots.
    if (i < (N_REL * DIM * DIM) / 4) {       // 16384 threads
        const float4 v4 = ((const float4*)relation)[i];
        const int base = i * 4;
        const float vv[4] = { v4.x, v4.y, v4.z, v4.w };
        #pragma unroll
        for (int q = 0; q < 4; ++q) {
            const int idx = base + q;
            const int r = idx >> 10, rem = idx & 1023;
            const int k = rem >> 5, e = rem & 31;
            bfrag_scatter(r, k, e, vv[q]);
        }
    }
    if (i < DIM * DIM) {
        const int d = i >> 5, e = i & 31;
        g_Wt[e * DIM + d] = W[i];
    }
}

// ---------------------------------------------------------------- GEMM (R13, proven)
__device__ __forceinline__ void mma16816(float c[4], const unsigned* a,
                                         unsigned b0, unsigned b1) {
    asm volatile(
        "mma.sync.aligned.m16n8k16.row.col.f32.bf16.bf16.f32 "
        "{%0,%1,%2,%3}, {%4,%5,%6,%7}, {%8,%9}, {%0,%1,%2,%3};\n"
        : "+f"(c[0]), "+f"(c[1]), "+f"(c[2]), "+f"(c[3])
        : "r"(a[0]), "r"(a[1]), "r"(a[2]), "r"(a[3]), "r"(b0), "r"(b1));
}

constexpr int OSTR = 144;   // bytes per sO row (128 payload + 16 pad)

// 256 blocks = one wave. Block (mt, ng): n-tiles ng*4..+3 of m-tile mt.
// A-frags loaded ONCE; B double-buffered at half-tile grain.
__global__ void __launch_bounds__(256, 3) gemm_kernel() {
    __shared__ __align__(16) char sO[8][16 * OSTR];   // per-warp slice, 18 KB

    const int lane = threadIdx.x & 31;
    const int warp = threadIdx.x >> 5;
    const int mt = blockIdx.x >> 3;
    const int ng = blockIdx.x & 7;
    const int mg = mt * 8 + warp;
    const int m0 = mt * 128;

    const uint4* __restrict__ Af = (const uint4*)g_Afrag;
    const uint4* __restrict__ Bf = (const uint4*)g_Bfrag;
    char* __restrict__ so = sO[warp];
    char* __restrict__ gU = (char*)g_U;

    const uint4 qa0 = Af[(mg * 2 + 0) * 32 + lane];   // k 0-15
    const uint4 qa1 = Af[(mg * 2 + 1) * 32 + lane];   // k 16-31

    uint4 buf[2][4];
    {
        const int nt = ng * 4;
        #pragma unroll
        for (int jj = 0; jj < 4; ++jj)
            buf[0][jj] = Bf[(nt * 8 + jj) * 32 + lane];
    }

    #pragma unroll
    for (int ht = 0; ht < 8; ++ht) {
        if (ht < 7) {
            const int ntn = ng * 4 + ((ht + 1) >> 1);
            const int jb  = ((ht + 1) & 1) * 4;
            #pragma unroll
            for (int jj = 0; jj < 4; ++jj)
                buf[(ht + 1) & 1][jj] = Bf[(ntn * 8 + jb + jj) * 32 + lane];
        }

        const uint4* qb = buf[ht & 1];
        #pragma unroll
        for (int jj = 0; jj < 4; ++jj) {
            const int j = (ht & 1) * 4 + jj;
            float c[4] = {0.f, 0.f, 0.f, 0.f};
            mma16816(c, (const unsigned*)&qa0, qb[jj].x, qb[jj].y);
            mma16816(c, (const unsigned*)&qa1, qb[jj].z, qb[jj].w);
            const __nv_bfloat162 p01 = __float22bfloat162_rn(make_float2(c[0], c[1]));
            const __nv_bfloat162 p23 = __float22bfloat162_rn(make_float2(c[2], c[3]));
            const int row  = lane >> 2;
            const int colb = (8 * j + 2 * (lane & 3)) * 2;
            *(__nv_bfloat162*)(so + row * OSTR + colb)       = p01;
            *(__nv_bfloat162*)(so + (row + 8) * OSTR + colb) = p23;
        }

        if (ht & 1) {
            __syncwarp();
            const int n0 = (ng * 4 + (ht >> 1)) * 64;
            #pragma unroll
            for (int i = 0; i < 4; ++i) {
                const int idx = lane + 32 * i;
                const int row = idx >> 3, ch = idx & 7;
                const uint4 v = *(const uint4*)(so + row * OSTR + ch * 16);
                *(uint4*)(gU + ((size_t)(m0 + warp * 16 + row) * NCOL + n0) * 2
                          + ch * 16) = v;
            }
            __syncwarp();
        }
    }
}

// ---------------------------------------------------------------- attention (R13, proven)
constexpr int AW = 8;

__global__ void __launch_bounds__(256, 3) attn_kernel(
    const int* __restrict__ mem_h,
    const int* __restrict__ mem_r,
    const int* __restrict__ mem_t,
    const int* __restrict__ users,
    const float* __restrict__ entity,
    const float* __restrict__ user_table,
    float* __restrict__ out,
    int hop, int last)
{
    __shared__ float P[AW][2][N_MEM * 9];

    const int lane = threadIdx.x & 31;
    const int warp = threadIdx.x >> 5;
    const int b0 = (blockIdx.x * AW + warp) * 2;
    const int b1 = b0 + 1;
    float* __restrict__ P0 = P[warp][0];
    float* __restrict__ P1 = P[warp][1];

    const int base0 = hop * BATCH * N_MEM + b0 * N_MEM;
    const int base1 = base0 + N_MEM;
    const int hidx0 = mem_h[base0 + lane], hidx1 = mem_h[base1 + lane];
    const int ridx0 = mem_r[base0 + lane], ridx1 = mem_r[base1 + lane];
    const int tidx0 = mem_t[base0 + lane], tidx1 = mem_t[base1 + lane];

    const float item0 = g_item[b0 * DIM + lane];
    const float item1 = g_item[b1 * DIM + lane];

    const int mq = lane >> 3;
    const int c  = lane & 7;
    const __nv_bfloat16* __restrict__ U0 = g_U + (size_t)b0 * NCOL;
    const __nv_bfloat16* __restrict__ U1 = g_U + (size_t)b1 * NCOL;

    #pragma unroll
    for (int ss = 0; ss < 4; ++ss) {
        uint2  uu0[2], uu1[2];
        float4 h40[2], h41[2];
        #pragma unroll
        for (int it = 0; it < 2; ++it) {
            const int m = ss * 8 + it * 4 + mq;
            const int r0 = __shfl_sync(FULL, ridx0, m);
            const int h0 = __shfl_sync(FULL, hidx0, m);
            const int r1 = __shfl_sync(FULL, ridx1, m);
            const int h1 = __shfl_sync(FULL, hidx1, m);
            uu0[it] = *(const uint2*)(U0 + r0 * DIM + 4 * c);
            h40[it] = *(const float4*)(entity + h0 * DIM + 4 * c);
            uu1[it] = *(const uint2*)(U1 + r1 * DIM + 4 * c);
            h41[it] = *(const float4*)(entity + h1 * DIM + 4 * c);
        }
        #pragma unroll
        for (int it = 0; it < 2; ++it) {
            const int m = ss * 8 + it * 4 + mq;
            P0[m * 9 + c] = bf_lo(uu0[it].x) * h40[it].x + bf_hi(uu0[it].x) * h40[it].y +
                            bf_lo(uu0[it].y) * h40[it].z + bf_hi(uu0[it].y) * h40[it].w;
            P1[m * 9 + c] = bf_lo(uu1[it].x) * h41[it].x + bf_hi(uu1[it].x) * h41[it].y +
                            bf_lo(uu1[it].y) * h41[it].z + bf_hi(uu1[it].y) * h41[it].w;
        }
    }
    __syncwarp();

    float lg0 = 0.f, lg1 = 0.f;
    #pragma unroll
    for (int j = 0; j < 8; ++j) { lg0 += P0[lane * 9 + j]; lg1 += P1[lane * 9 + j]; }

    float mx0 = lg0, mx1 = lg1;
    #pragma unroll
    for (int off = 16; off; off >>= 1) {
        mx0 = fmaxf(mx0, __shfl_xor_sync(FULL, mx0, off));
        mx1 = fmaxf(mx1, __shfl_xor_sync(FULL, mx1, off));
    }
    const float ex0 = __expf(lg0 - mx0);
    const float ex1 = __expf(lg1 - mx1);
    float dn0 = ex0, dn1 = ex1;
    #pragma unroll
    for (int off = 16; off; off >>= 1) {
        dn0 += __shfl_xor_sync(FULL, dn0, off);
        dn1 += __shfl_xor_sync(FULL, dn1, off);
    }
    const float prob0 = ex0 / dn0;
    const float prob1 = ex1 / dn1;

    float o0 = 0.f, o1 = 0.f;
    #pragma unroll 8
    for (int m = 0; m < N_MEM; ++m) {
        const int t0 = __shfl_sync(FULL, tidx0, m);
        const int t1 = __shfl_sync(FULL, tidx1, m);
        const float p0 = __shfl_sync(FULL, prob0, m);
        const float p1 = __shfl_sync(FULL, prob1, m);
        o0 = fmaf(p0, entity[t0 * DIM + lane], o0);
        o1 = fmaf(p1, entity[t1 * DIM + lane], o1);
    }

    const float tmp0 = item0 + o0, tmp1 = item1 + o1;
    float itn0 = 0.f, itn1 = 0.f;
    #pragma unroll
    for (int e = 0; e < DIM; ++e) {
        const float w = g_Wt[e * DIM + lane];
        itn0 = fmaf(__shfl_sync(FULL, tmp0, e), w, itn0);
        itn1 = fmaf(__shfl_sync(FULL, tmp1, e), w, itn1);
    }

    if (!last) {
        g_item[b0 * DIM + lane] = itn0;
        g_item[b1 * DIM + lane] = itn1;
        g_y[b0 * DIM + lane] = o0;
        g_y[b1 * DIM + lane] = o1;
        afrag_store(b0, lane, itn0);
        afrag_store(b1, lane, itn1);
    } else {
        const float y0 = g_y[b0 * DIM + lane] + o0 + user_table[users[b0] * DIM + lane];
        const float y1 = g_y[b1 * DIM + lane] + o1 + user_table[users[b1] * DIM + lane];
        float s0 = itn0 * y0, s1 = itn1 * y1;
        #pragma unroll
        for (int off = 16; off; off >>= 1) {
            s0 += __shfl_xor_sync(FULL, s0, off);
            s1 += __shfl_xor_sync(FULL, s1, off);
        }
        if (lane == 0) {
            out[b0] = 1.f / (1.f + __expf(-s0));
            out[b1] = 1.f / (1.f + __expf(-s1));
        }
    }
}

// ---------------------------------------------------------------- launch
extern "C" void kernel_launch(void* const* d_in, const int* in_sizes, int n_in,
                              void* d_out, int out_size) {
    const int*   items     = (const int*)d_in[0];
    const int*   mem_h     = (const int*)d_in[2];
    const int*   mem_r     = (const int*)d_in[3];
    const int*   mem_t     = (const int*)d_in[4];
    const int*   users     = (const int*)d_in[5];
    const float* entity    = (const float*)d_in[6];
    const float* relation  = (const float*)d_in[7];
    const float* user_tab  = (const float*)d_in[8];
    const float* W         = (const float*)d_in[9];
    float* out = (float*)d_out;

    prep_kernel<<<(BATCH * DIM + 255) / 256, 256>>>(items, entity, relation, W);

    gemm_kernel<<<256, 256>>>();
    attn_kernel<<<BATCH / (AW * 2), 256>>>(mem_h, mem_r, mem_t, users,
                                           entity, user_tab, out, 0, 0);
    gemm_kernel<<<256, 256>>>();
    attn_kernel<<<BATCH / (AW * 2), 256>>>(mem_h, mem_r, mem_t, users,
                                           entity, user_tab, out, 1, 1);
}